// round 9
// baseline (speedup 1.0000x reference)
#include <cuda_runtime.h>
#include <cuda_bf16.h>
#include <mma.h>
#include <cstdint>

using namespace nvcuda;

#define B_  8
#define S_  512
#define KV_ 2048
#define NH_ 16
#define HD_ 64
#define D_  1024

// bf16 scratch buffers
__device__ __nv_bfloat16 d_kbf[(size_t)B_ * NH_ * KV_ * HD_];     // [bh][kv][d]
__device__ __nv_bfloat16 d_vbf[(size_t)B_ * NH_ * KV_ * HD_];     // [bh][kv][d]
__device__ __nv_bfloat16 d_hbf[(size_t)B_ * S_ * D_];
__device__ __nv_bfloat16 d_wbf[(size_t)D_ * D_];
__device__ __nv_bfloat16 d_qscratch[(size_t)B_ * NH_ * S_ * HD_]; // [bh][s][d]

// split-KV partials: p = (b*NH+h)*8+st in [0,1024), half in {0,1}
__device__ float d_po [(size_t)1024 * 2 * 64 * 64];  // unnormalized O, 33.5 MB
__device__ float d_prs[(size_t)1024 * 2 * 64];       // partial rowsums

// ---------------------------------------------------------------------------
// PTX helpers
// ---------------------------------------------------------------------------
__device__ __forceinline__ void ldsm4(uint32_t* r, uint32_t a) {
    asm volatile("ldmatrix.sync.aligned.m8n8.x4.shared.b16 {%0,%1,%2,%3}, [%4];\n"
        : "=r"(r[0]), "=r"(r[1]), "=r"(r[2]), "=r"(r[3]) : "r"(a));
}
__device__ __forceinline__ void ldsm4t(uint32_t* r, uint32_t a) {
    asm volatile("ldmatrix.sync.aligned.m8n8.x4.trans.shared.b16 {%0,%1,%2,%3}, [%4];\n"
        : "=r"(r[0]), "=r"(r[1]), "=r"(r[2]), "=r"(r[3]) : "r"(a));
}
__device__ __forceinline__ void mma16816(float* c, const uint32_t* a, uint32_t b0, uint32_t b1) {
    asm volatile("mma.sync.aligned.m16n8k16.row.col.f32.bf16.bf16.f32 "
        "{%0,%1,%2,%3}, {%4,%5,%6,%7}, {%8,%9}, {%0,%1,%2,%3};\n"
        : "+f"(c[0]), "+f"(c[1]), "+f"(c[2]), "+f"(c[3])
        : "r"(a[0]), "r"(a[1]), "r"(a[2]), "r"(a[3]), "r"(b0), "r"(b1));
}
#define CP16(dst, src) asm volatile("cp.async.cg.shared.global [%0], [%1], 16;\n" :: "r"(dst), "l"(src))
#define CP_COMMIT()    asm volatile("cp.async.commit_group;\n")
#define CP_WAIT0()     asm volatile("cp.async.wait_group 0;\n")

__device__ __forceinline__ uint32_t pack_bf2(float a, float b) {
    __nv_bfloat162 t = __float22bfloat162_rn(make_float2(a, b));
    return *(uint32_t*)&t;
}
#define SWZ128(x) ((x) ^ (((x) >> 3) & 0x70))

// ---------------------------------------------------------------------------
// fp32 -> bf16 conversion
// ---------------------------------------------------------------------------
__global__ __launch_bounds__(256)
void cvt_kernel(const float4* __restrict__ src, float2* __restrict__ dst, int n4)
{
    int i = blockIdx.x * blockDim.x + threadIdx.x;
    if (i < n4) {
        float4 v = src[i];
        __nv_bfloat162 o[2];
        o[0] = __float22bfloat162_rn(make_float2(v.x, v.y));
        o[1] = __float22bfloat162_rn(make_float2(v.z, v.w));
        dst[i] = *(float2*)o;
    }
}

// ---------------------------------------------------------------------------
// Q projection — unchanged (known-good)
// ---------------------------------------------------------------------------
__global__ __launch_bounds__(256)
void qproj_kernel()
{
    __shared__ __align__(16) char smem_raw[2 * 128 * 72 * 2];
    __nv_bfloat16* As = (__nv_bfloat16*)smem_raw;
    __nv_bfloat16* Bs = As + 128 * 72;
    float* Cs = (float*)smem_raw;

    const int n0 = blockIdx.x * 128;
    const int m0 = blockIdx.y * 128;
    const int tid = threadIdx.x;
    const int wid = tid >> 5;
    const int wr = wid & 3;
    const int wc = wid >> 2;

    wmma::fragment<wmma::accumulator, 16, 16, 16, float> acc[2][4];
    #pragma unroll
    for (int i = 0; i < 2; i++)
        #pragma unroll
        for (int j = 0; j < 4; j++) wmma::fill_fragment(acc[i][j], 0.0f);

    for (int kt = 0; kt < 16; kt++) {
        const int k0 = kt * 64;
        for (int i = tid; i < 128 * 8; i += 256) {
            int r = i >> 3, c = (i & 7) * 8;
            *(uint4*)&As[r * 72 + c] = *(const uint4*)(d_hbf + (size_t)(m0 + r) * D_ + k0 + c);
            *(uint4*)&Bs[r * 72 + c] = *(const uint4*)(d_wbf + (size_t)(n0 + r) * D_ + k0 + c);
        }
        __syncthreads();
        #pragma unroll
        for (int ks = 0; ks < 4; ks++) {
            wmma::fragment<wmma::matrix_a, 16, 16, 16, __nv_bfloat16, wmma::row_major> af[2];
            wmma::load_matrix_sync(af[0], &As[(wr * 32 + 0)  * 72 + ks * 16], 72);
            wmma::load_matrix_sync(af[1], &As[(wr * 32 + 16) * 72 + ks * 16], 72);
            #pragma unroll
            for (int j = 0; j < 4; j++) {
                wmma::fragment<wmma::matrix_b, 16, 16, 16, __nv_bfloat16, wmma::col_major> bf;
                wmma::load_matrix_sync(bf, &Bs[(wc * 64 + j * 16) * 72 + ks * 16], 72);
                wmma::mma_sync(acc[0][j], af[0], bf, acc[0][j]);
                wmma::mma_sync(acc[1][j], af[1], bf, acc[1][j]);
            }
        }
        __syncthreads();
    }

    #pragma unroll
    for (int half = 0; half < 2; half++) {
        __syncthreads();
        if ((wr >> 1) == half) {
            const int lr = (wr & 1) * 32;
            #pragma unroll
            for (int i = 0; i < 2; i++)
                #pragma unroll
                for (int j = 0; j < 4; j++)
                    wmma::store_matrix_sync(&Cs[(lr + i * 16) * 132 + wc * 64 + j * 16],
                                            acc[i][j], 132, wmma::mem_row_major);
        }
        __syncthreads();
        for (int i = tid; i < 64 * 16; i += 256) {
            int r = i >> 4, c8 = (i & 15) * 8;
            int gm = m0 + half * 64 + r;
            int gn = n0 + c8;
            int b = gm >> 9, s = gm & 511;
            int h = gn >> 6, d = gn & 63;
            const float* src = &Cs[r * 132 + c8];
            __nv_bfloat162 o[4];
            o[0] = __float22bfloat162_rn(make_float2(src[0], src[1]));
            o[1] = __float22bfloat162_rn(make_float2(src[2], src[3]));
            o[2] = __float22bfloat162_rn(make_float2(src[4], src[5]));
            o[3] = __float22bfloat162_rn(make_float2(src[6], src[7]));
            *(uint4*)(d_qscratch + (((size_t)(b * NH_ + h) * S_ + s) * HD_ + d)) = *(uint4*)o;
        }
    }
}

// ---------------------------------------------------------------------------
// Fused flash attention, split-KV = 2.
// CTA = 64 queries x 1024 KV positions (16 tiles of 64). Writes unnormalized
// partial O + partial rowsums to scratch; combine kernel finishes.
// grid (16 = st*2+half, 16 heads, 8 batch), 128 threads, 5 CTAs/SM.
// ---------------------------------------------------------------------------
#define NT2 16   // KV tiles per half

__global__ __launch_bounds__(128, 5)
void attn_kernel(const float* __restrict__ Mg_)
{
    __shared__ __align__(1024) __nv_bfloat16 sK[2][64 * 64];
    __shared__ __align__(1024) __nv_bfloat16 sV[2][64 * 64];
    __shared__ __align__(16)   float         sM[2][64];

    const int st = blockIdx.x >> 1, half = blockIdx.x & 1;
    const int h = blockIdx.y, b = blockIdx.z;
    const size_t bh = (size_t)b * NH_ + h;
    const int kvbase = half * (KV_ / 2);
    const __nv_bfloat16* Kh = d_kbf + bh * KV_ * HD_;
    const __nv_bfloat16* Vh = d_vbf + bh * KV_ * HD_;
    const float* Mg = Mg_ + (size_t)b * KV_;

    const int tid = threadIdx.x;
    const int wid = tid >> 5;
    const int lane = tid & 31;

    const uint32_t ks_b = (uint32_t)__cvta_generic_to_shared(sK[0]);
    const uint32_t vs_b = (uint32_t)__cvta_generic_to_shared(sV[0]);
    const uint32_t ms_b = (uint32_t)__cvta_generic_to_shared(sM[0]);

    // one KV tile (K + V + mask) -> swizzled buffer `buf`, one commit group
    auto load_tile = [&](int buf, int kv0) {
        #pragma unroll
        for (int i = 0; i < 4; i++) {
            int idx = tid + i * 128;                 // 512 chunks of 16B
            int r = idx >> 3, c16 = (idx & 7) * 16;
            uint32_t off = (uint32_t)(buf * 8192) + SWZ128((uint32_t)(r * 128 + c16));
            CP16(ks_b + off, Kh + (size_t)(kv0 + r) * HD_ + c16 / 2);
            CP16(vs_b + off, Vh + (size_t)(kv0 + r) * HD_ + c16 / 2);
        }
        if (tid < 16) CP16(ms_b + (uint32_t)(buf * 256 + tid * 16), Mg + kv0 + tid * 4);
    };

    load_tile(0, kvbase);
    CP_COMMIT();      // group 0

    // Q fragments loaded directly from gmem in the standard mma A-layout
    const int m0 = wid * 16;
    const __nv_bfloat16* Qg = d_qscratch + (bh * S_ + st * 64) * HD_;
    uint32_t qf[4][4];
    {
        const int r0 = m0 + (lane >> 2);
        const int cb = (lane & 3) * 2;
        #pragma unroll
        for (int kb = 0; kb < 4; kb++) {
            qf[kb][0] = *(const uint32_t*)(Qg + (size_t)r0 * HD_ + kb * 16 + cb);
            qf[kb][1] = *(const uint32_t*)(Qg + (size_t)(r0 + 8) * HD_ + kb * 16 + cb);
            qf[kb][2] = *(const uint32_t*)(Qg + (size_t)r0 * HD_ + kb * 16 + cb + 8);
            qf[kb][3] = *(const uint32_t*)(Qg + (size_t)(r0 + 8) * HD_ + kb * 16 + cb + 8);
        }
    }

    float oacc[8][4];
    #pragma unroll
    for (int i = 0; i < 8; i++)
        #pragma unroll
        for (int j = 0; j < 4; j++) oacc[i][j] = 0.0f;
    float rs0 = 0.0f, rs1 = 0.0f;

    // lane-derived ldsm address components
    const int lrow = (lane & 7) + ((lane >> 3) & 1) * 8;   // row within 16-chunk
    const int lcolb = ((lane >> 4) & 1) * 16;              // byte col within 32B

    for (int t = 0; t < NT2; t++) {
        const int cur = t & 1;
        const uint32_t kbase = ks_b + (uint32_t)cur * 8192;
        const uint32_t vbase = vs_b + (uint32_t)cur * 8192;
        const float* mrow = sM[cur];

        CP_WAIT0();        // tile t resident
        __syncthreads();   // visible to all warps; WAR fence for buf^1

        if (t + 1 < NT2) load_tile(cur ^ 1, kvbase + (t + 1) * 64);
        CP_COMMIT();

        #pragma unroll
        for (int hv = 0; hv < 2; hv++) {       // two 32-kv halves
            // ---- S = Q K^T for kv cols [hv*32, hv*32+32) ----
            float sacc[4][4];
            #pragma unroll
            for (int i = 0; i < 4; i++)
                #pragma unroll
                for (int j = 0; j < 4; j++) sacc[i][j] = 0.0f;

            #pragma unroll
            for (int kb = 0; kb < 4; kb++) {
                #pragma unroll
                for (int nb2 = 0; nb2 < 2; nb2++) {
                    uint32_t kr[4];
                    int row = hv * 32 + nb2 * 16 + lrow;
                    int colb = kb * 32 + lcolb;
                    ldsm4(kr, kbase + SWZ128((uint32_t)(row * 128 + colb)));
                    mma16816(sacc[nb2 * 2 + 0], qf[kb], kr[0], kr[2]);
                    mma16816(sacc[nb2 * 2 + 1], qf[kb], kr[1], kr[3]);
                }
            }

            // ---- exp + PV interleaved per 16-kv chunk ----
            #pragma unroll
            for (int kvc = 0; kvc < 2; kvc++) {
                uint32_t pf[4];
                #pragma unroll
                for (int hh = 0; hh < 2; hh++) {
                    const int nb = kvc * 2 + hh;
                    const int c0 = hv * 32 + nb * 8 + (lane & 3) * 2;
                    float mv0 = mrow[c0], mv1 = mrow[c0 + 1];
                    float p0 = __expf(sacc[nb][0] + mv0);
                    float p1 = __expf(sacc[nb][1] + mv1);
                    float p2 = __expf(sacc[nb][2] + mv0);
                    float p3 = __expf(sacc[nb][3] + mv1);
                    rs0 += p0 + p1;
                    rs1 += p2 + p3;
                    pf[hh * 2 + 0] = pack_bf2(p0, p1);
                    pf[hh * 2 + 1] = pack_bf2(p2, p3);
                }
                #pragma unroll
                for (int nb2 = 0; nb2 < 4; nb2++) {
                    uint32_t vr[4];
                    int vrow = hv * 32 + kvc * 16 + lrow;
                    int vcolb = nb2 * 32 + lcolb;
                    ldsm4t(vr, vbase + SWZ128((uint32_t)(vrow * 128 + vcolb)));
                    mma16816(oacc[nb2 * 2 + 0], pf, vr[0], vr[1]);
                    mma16816(oacc[nb2 * 2 + 1], pf, vr[2], vr[3]);
                }
            }
        }
        // no trailing sync: next iteration's top sync is the WAR fence
    }

    // finalize rowsums across the quad
    rs0 += __shfl_xor_sync(0xffffffffu, rs0, 1);
    rs0 += __shfl_xor_sync(0xffffffffu, rs0, 2);
    rs1 += __shfl_xor_sync(0xffffffffu, rs1, 1);
    rs1 += __shfl_xor_sync(0xffffffffu, rs1, 2);

    // write unnormalized partials to scratch
    const int p2 = ((int)bh * 8 + st) * 2 + half;
    float* Po  = d_po  + (size_t)p2 * 64 * 64;
    float* Prs = d_prs + (size_t)p2 * 64;
    const int r0 = m0 + (lane >> 2);
    const int c0 = (lane & 3) * 2;
    if ((lane & 3) == 0) { Prs[r0] = rs0; Prs[r0 + 8] = rs1; }
    #pragma unroll
    for (int nb = 0; nb < 8; nb++) {
        *(float2*)(Po + (size_t)r0 * 64 + nb * 8 + c0)       = make_float2(oacc[nb][0], oacc[nb][1]);
        *(float2*)(Po + (size_t)(r0 + 8) * 64 + nb * 8 + c0) = make_float2(oacc[nb][2], oacc[nb][3]);
    }
}

// ---------------------------------------------------------------------------
// Combine: out = (O0 + O1) / (rs0 + rs1), scattered to [b, s, h*64+c].
// 1,048,576 float4 items; grid 4096 x 256.
// ---------------------------------------------------------------------------
__global__ __launch_bounds__(256)
void combine_kernel(float* __restrict__ out)
{
    int idx = blockIdx.x * 256 + threadIdx.x;   // 0 .. 1,048,575
    int row = idx >> 4;                         // p*64 + r, 65536 rows
    int c4 = (idx & 15) * 4;
    int p = row >> 6, r = row & 63;

    const float* P0 = d_po + ((size_t)(p * 2 + 0) * 64 + r) * 64 + c4;
    const float* P1 = d_po + ((size_t)(p * 2 + 1) * 64 + r) * 64 + c4;
    float rs = d_prs[(size_t)(p * 2 + 0) * 64 + r] + d_prs[(size_t)(p * 2 + 1) * 64 + r];
    float inv = 1.0f / rs;

    float4 a = *(const float4*)P0;
    float4 b4 = *(const float4*)P1;
    float4 o = make_float4((a.x + b4.x) * inv, (a.y + b4.y) * inv,
                           (a.z + b4.z) * inv, (a.w + b4.w) * inv);

    int bb = p >> 7, hh = (p >> 3) & 15, st = p & 7;
    size_t off = ((size_t)(bb * S_ + st * 64 + r) * D_) + hh * HD_ + c4;
    *(float4*)(out + off) = o;
}

// ---------------------------------------------------------------------------
// Launch
// ---------------------------------------------------------------------------
extern "C" void kernel_launch(void* const* d_in, const int* in_sizes, int n_in,
                              void* d_out, int out_size)
{
    const float* H  = (const float*)d_in[0];  // [8,512,1024]
    const float* Wq = (const float*)d_in[1];  // [1024,1024]
    const float* K  = (const float*)d_in[2];  // [8,16,2048,64]
    const float* V  = (const float*)d_in[3];  // [8,16,2048,64]
    const float* M  = (const float*)d_in[4];  // [8,2048]
    float* out = (float*)d_out;               // [8,512,1024]

    __nv_bfloat16 *kb, *vb, *hb, *wb;
    cudaGetSymbolAddress((void**)&kb, d_kbf);
    cudaGetSymbolAddress((void**)&vb, d_vbf);
    cudaGetSymbolAddress((void**)&hb, d_hbf);
    cudaGetSymbolAddress((void**)&wb, d_wbf);

    const int nKV4 = (B_ * NH_ * KV_ * HD_) / 4;   // 4,194,304
    const int nH4  = (B_ * S_ * D_) / 4;           // 1,048,576
    const int nW4  = (D_ * D_) / 4;                // 262,144

    cvt_kernel<<<(nKV4 + 255) / 256, 256>>>((const float4*)K, (float2*)kb, nKV4);
    cvt_kernel<<<(nKV4 + 255) / 256, 256>>>((const float4*)V, (float2*)vb, nKV4);
    cvt_kernel<<<(nH4 + 255) / 256, 256>>>((const float4*)H, (float2*)hb, nH4);
    cvt_kernel<<<(nW4 + 255) / 256, 256>>>((const float4*)Wq, (float2*)wb, nW4);

    qproj_kernel<<<dim3(8, 32), 256>>>();
    attn_kernel<<<dim3(16, 16, 8), 128>>>(M);
    combine_kernel<<<4096, 256>>>(out);
}

// round 10
// speedup vs baseline: 1.0049x; 1.0049x over previous
#include <cuda_runtime.h>
#include <cuda_bf16.h>
#include <mma.h>
#include <cstdint>

using namespace nvcuda;

#define B_  8
#define S_  512
#define KV_ 2048
#define NH_ 16
#define HD_ 64
#define D_  1024

// bf16 scratch buffers
__device__ __nv_bfloat16 d_kbf[(size_t)B_ * NH_ * KV_ * HD_];     // [bh][kv][d]
__device__ __nv_bfloat16 d_vbf[(size_t)B_ * NH_ * KV_ * HD_];     // [bh][kv][d]
__device__ __nv_bfloat16 d_hbf[(size_t)B_ * S_ * D_];
__device__ __nv_bfloat16 d_wbf[(size_t)D_ * D_];
__device__ __nv_bfloat16 d_qscratch[(size_t)B_ * NH_ * S_ * HD_]; // [bh][s][d]

// ---------------------------------------------------------------------------
// PTX helpers
// ---------------------------------------------------------------------------
__device__ __forceinline__ void ldsm4(uint32_t* r, uint32_t a) {
    asm volatile("ldmatrix.sync.aligned.m8n8.x4.shared.b16 {%0,%1,%2,%3}, [%4];\n"
        : "=r"(r[0]), "=r"(r[1]), "=r"(r[2]), "=r"(r[3]) : "r"(a));
}
__device__ __forceinline__ void ldsm4t(uint32_t* r, uint32_t a) {
    asm volatile("ldmatrix.sync.aligned.m8n8.x4.trans.shared.b16 {%0,%1,%2,%3}, [%4];\n"
        : "=r"(r[0]), "=r"(r[1]), "=r"(r[2]), "=r"(r[3]) : "r"(a));
}
__device__ __forceinline__ void mma16816(float* c, const uint32_t* a, uint32_t b0, uint32_t b1) {
    asm volatile("mma.sync.aligned.m16n8k16.row.col.f32.bf16.bf16.f32 "
        "{%0,%1,%2,%3}, {%4,%5,%6,%7}, {%8,%9}, {%0,%1,%2,%3};\n"
        : "+f"(c[0]), "+f"(c[1]), "+f"(c[2]), "+f"(c[3])
        : "r"(a[0]), "r"(a[1]), "r"(a[2]), "r"(a[3]), "r"(b0), "r"(b1));
}
#define CP16(dst, src) asm volatile("cp.async.cg.shared.global [%0], [%1], 16;\n" :: "r"(dst), "l"(src))
#define CP_COMMIT()    asm volatile("cp.async.commit_group;\n")
#define CP_WAIT0()     asm volatile("cp.async.wait_group 0;\n")

__device__ __forceinline__ uint32_t pack_bf2(float a, float b) {
    __nv_bfloat162 t = __float22bfloat162_rn(make_float2(a, b));
    return *(uint32_t*)&t;
}
#define SWZ128(x) ((x) ^ (((x) >> 3) & 0x70))

// ---------------------------------------------------------------------------
// fp32 -> bf16 conversion
// ---------------------------------------------------------------------------
__global__ __launch_bounds__(256)
void cvt_kernel(const float4* __restrict__ src, float2* __restrict__ dst, int n4)
{
    int i = blockIdx.x * blockDim.x + threadIdx.x;
    if (i < n4) {
        float4 v = src[i];
        __nv_bfloat162 o[2];
        o[0] = __float22bfloat162_rn(make_float2(v.x, v.y));
        o[1] = __float22bfloat162_rn(make_float2(v.z, v.w));
        dst[i] = *(float2*)o;
    }
}

// ---------------------------------------------------------------------------
// Q projection — unchanged (known-good)
// ---------------------------------------------------------------------------
__global__ __launch_bounds__(256)
void qproj_kernel()
{
    __shared__ __align__(16) char smem_raw[2 * 128 * 72 * 2];
    __nv_bfloat16* As = (__nv_bfloat16*)smem_raw;
    __nv_bfloat16* Bs = As + 128 * 72;
    float* Cs = (float*)smem_raw;

    const int n0 = blockIdx.x * 128;
    const int m0 = blockIdx.y * 128;
    const int tid = threadIdx.x;
    const int wid = tid >> 5;
    const int wr = wid & 3;
    const int wc = wid >> 2;

    wmma::fragment<wmma::accumulator, 16, 16, 16, float> acc[2][4];
    #pragma unroll
    for (int i = 0; i < 2; i++)
        #pragma unroll
        for (int j = 0; j < 4; j++) wmma::fill_fragment(acc[i][j], 0.0f);

    for (int kt = 0; kt < 16; kt++) {
        const int k0 = kt * 64;
        for (int i = tid; i < 128 * 8; i += 256) {
            int r = i >> 3, c = (i & 7) * 8;
            *(uint4*)&As[r * 72 + c] = *(const uint4*)(d_hbf + (size_t)(m0 + r) * D_ + k0 + c);
            *(uint4*)&Bs[r * 72 + c] = *(const uint4*)(d_wbf + (size_t)(n0 + r) * D_ + k0 + c);
        }
        __syncthreads();
        #pragma unroll
        for (int ks = 0; ks < 4; ks++) {
            wmma::fragment<wmma::matrix_a, 16, 16, 16, __nv_bfloat16, wmma::row_major> af[2];
            wmma::load_matrix_sync(af[0], &As[(wr * 32 + 0)  * 72 + ks * 16], 72);
            wmma::load_matrix_sync(af[1], &As[(wr * 32 + 16) * 72 + ks * 16], 72);
            #pragma unroll
            for (int j = 0; j < 4; j++) {
                wmma::fragment<wmma::matrix_b, 16, 16, 16, __nv_bfloat16, wmma::col_major> bf;
                wmma::load_matrix_sync(bf, &Bs[(wc * 64 + j * 16) * 72 + ks * 16], 72);
                wmma::mma_sync(acc[0][j], af[0], bf, acc[0][j]);
                wmma::mma_sync(acc[1][j], af[1], bf, acc[1][j]);
            }
        }
        __syncthreads();
    }

    #pragma unroll
    for (int half = 0; half < 2; half++) {
        __syncthreads();
        if ((wr >> 1) == half) {
            const int lr = (wr & 1) * 32;
            #pragma unroll
            for (int i = 0; i < 2; i++)
                #pragma unroll
                for (int j = 0; j < 4; j++)
                    wmma::store_matrix_sync(&Cs[(lr + i * 16) * 132 + wc * 64 + j * 16],
                                            acc[i][j], 132, wmma::mem_row_major);
        }
        __syncthreads();
        for (int i = tid; i < 64 * 16; i += 256) {
            int r = i >> 4, c8 = (i & 15) * 8;
            int gm = m0 + half * 64 + r;
            int gn = n0 + c8;
            int b = gm >> 9, s = gm & 511;
            int h = gn >> 6, d = gn & 63;
            const float* src = &Cs[r * 132 + c8];
            __nv_bfloat162 o[4];
            o[0] = __float22bfloat162_rn(make_float2(src[0], src[1]));
            o[1] = __float22bfloat162_rn(make_float2(src[2], src[3]));
            o[2] = __float22bfloat162_rn(make_float2(src[4], src[5]));
            o[3] = __float22bfloat162_rn(make_float2(src[6], src[7]));
            *(uint4*)(d_qscratch + (((size_t)(b * NH_ + h) * S_ + s) * HD_ + d)) = *(uint4*)o;
        }
    }
}

// ---------------------------------------------------------------------------
// Fused flash attention, M=32 rows per warp (halves ldsm bytes per MAC).
// CTA = 128 queries (4 warps x 32 rows), 128 threads, KV tiles of 64
// processed in four kv-16 chunks (keeps sacc at 16 regs).
// smem: K[2][8KB] + V[2][8KB] + M[2][256B] = 33.3 KB.
// grid (4 s-tiles, 16 heads, 8 batch) = 512 CTAs (~single wave).
// ---------------------------------------------------------------------------
#define NT (KV_ / 64)

__global__ __launch_bounds__(128)
void attn_kernel(const float* __restrict__ Mg_, float* __restrict__ Out)
{
    __shared__ __align__(1024) __nv_bfloat16 sK[2][64 * 64];
    __shared__ __align__(1024) __nv_bfloat16 sV[2][64 * 64];
    __shared__ __align__(16)   float         sM[2][64];

    const int st = blockIdx.x, h = blockIdx.y, b = blockIdx.z;
    const size_t bh = (size_t)b * NH_ + h;
    const __nv_bfloat16* Kh = d_kbf + bh * KV_ * HD_;
    const __nv_bfloat16* Vh = d_vbf + bh * KV_ * HD_;
    const float* Mg = Mg_ + (size_t)b * KV_;

    const int tid = threadIdx.x;
    const int wid = tid >> 5;
    const int lane = tid & 31;

    const uint32_t ks_b = (uint32_t)__cvta_generic_to_shared(sK[0]);
    const uint32_t vs_b = (uint32_t)__cvta_generic_to_shared(sV[0]);
    const uint32_t ms_b = (uint32_t)__cvta_generic_to_shared(sM[0]);

    // one KV tile (K + V + mask) -> swizzled buffer `buf`, one commit group
    auto load_tile = [&](int buf, int kv0) {
        #pragma unroll
        for (int i = 0; i < 4; i++) {
            int idx = tid + i * 128;                 // 512 chunks of 16B
            int r = idx >> 3, c16 = (idx & 7) * 16;
            uint32_t off = (uint32_t)(buf * 8192) + SWZ128((uint32_t)(r * 128 + c16));
            CP16(ks_b + off, Kh + (size_t)(kv0 + r) * HD_ + c16 / 2);
            CP16(vs_b + off, Vh + (size_t)(kv0 + r) * HD_ + c16 / 2);
        }
        if (tid < 16) CP16(ms_b + (uint32_t)(buf * 256 + tid * 16), Mg + kv0 + tid * 4);
    };

    load_tile(0, 0);
    CP_COMMIT();      // group 0

    // Q fragments from gmem: 2 m-groups of 16 rows, 4 k-slices of 16
    const int m0 = wid * 32;
    const __nv_bfloat16* Qg = d_qscratch + (bh * S_ + st * 128) * HD_;
    uint32_t qf[2][4][4];
    {
        const int cb = (lane & 3) * 2;
        #pragma unroll
        for (int mg = 0; mg < 2; mg++) {
            const int r0 = m0 + mg * 16 + (lane >> 2);
            #pragma unroll
            for (int kb = 0; kb < 4; kb++) {
                qf[mg][kb][0] = *(const uint32_t*)(Qg + (size_t)r0 * HD_ + kb * 16 + cb);
                qf[mg][kb][1] = *(const uint32_t*)(Qg + (size_t)(r0 + 8) * HD_ + kb * 16 + cb);
                qf[mg][kb][2] = *(const uint32_t*)(Qg + (size_t)r0 * HD_ + kb * 16 + cb + 8);
                qf[mg][kb][3] = *(const uint32_t*)(Qg + (size_t)(r0 + 8) * HD_ + kb * 16 + cb + 8);
            }
        }
    }

    float oacc[2][8][4];
    #pragma unroll
    for (int mg = 0; mg < 2; mg++)
        #pragma unroll
        for (int i = 0; i < 8; i++)
            #pragma unroll
            for (int j = 0; j < 4; j++) oacc[mg][i][j] = 0.0f;
    float rs[2][2] = {{0.0f, 0.0f}, {0.0f, 0.0f}};

    // lane-derived ldsm address components
    const int lrow = (lane & 7) + ((lane >> 3) & 1) * 8;   // row within 16-chunk
    const int lcolb = ((lane >> 4) & 1) * 16;              // byte col within 32B

    for (int t = 0; t < NT; t++) {
        const int cur = t & 1;
        const uint32_t kbase = ks_b + (uint32_t)cur * 8192;
        const uint32_t vbase = vs_b + (uint32_t)cur * 8192;
        const float* mrow = sM[cur];

        CP_WAIT0();        // tile t resident
        __syncthreads();   // visible to all warps; WAR fence for buf^1

        if (t + 1 < NT) load_tile(cur ^ 1, (t + 1) * 64);
        CP_COMMIT();

        #pragma unroll
        for (int c = 0; c < 4; c++) {        // kv-16 chunks
            // ---- S = Q K^T for kv rows [c*16, c*16+16) ----
            float sacc[2][2][4];
            #pragma unroll
            for (int mg = 0; mg < 2; mg++)
                #pragma unroll
                for (int i = 0; i < 2; i++)
                    #pragma unroll
                    for (int j = 0; j < 4; j++) sacc[mg][i][j] = 0.0f;

            #pragma unroll
            for (int kb = 0; kb < 4; kb++) {
                uint32_t kr[4];
                int row = c * 16 + lrow;
                int colb = kb * 32 + lcolb;
                ldsm4(kr, kbase + SWZ128((uint32_t)(row * 128 + colb)));
                mma16816(sacc[0][0], qf[0][kb], kr[0], kr[2]);
                mma16816(sacc[0][1], qf[0][kb], kr[1], kr[3]);
                mma16816(sacc[1][0], qf[1][kb], kr[0], kr[2]);
                mma16816(sacc[1][1], qf[1][kb], kr[1], kr[3]);
            }

            // ---- exp + P fragments ----
            uint32_t pf[2][4];
            #pragma unroll
            for (int mg = 0; mg < 2; mg++) {
                #pragma unroll
                for (int ng = 0; ng < 2; ng++) {
                    const int c0 = c * 16 + ng * 8 + (lane & 3) * 2;
                    float mv0 = mrow[c0], mv1 = mrow[c0 + 1];
                    float p0 = __expf(sacc[mg][ng][0] + mv0);
                    float p1 = __expf(sacc[mg][ng][1] + mv1);
                    float p2 = __expf(sacc[mg][ng][2] + mv0);
                    float p3 = __expf(sacc[mg][ng][3] + mv1);
                    rs[mg][0] += p0 + p1;
                    rs[mg][1] += p2 + p3;
                    pf[mg][ng * 2 + 0] = pack_bf2(p0, p1);
                    pf[mg][ng * 2 + 1] = pack_bf2(p2, p3);
                }
            }

            // ---- O += P V ----
            #pragma unroll
            for (int nb2 = 0; nb2 < 4; nb2++) {
                uint32_t vr[4];
                int vrow = c * 16 + lrow;
                int vcolb = nb2 * 32 + lcolb;
                ldsm4t(vr, vbase + SWZ128((uint32_t)(vrow * 128 + vcolb)));
                mma16816(oacc[0][nb2 * 2 + 0], pf[0], vr[0], vr[1]);
                mma16816(oacc[0][nb2 * 2 + 1], pf[0], vr[2], vr[3]);
                mma16816(oacc[1][nb2 * 2 + 0], pf[1], vr[0], vr[1]);
                mma16816(oacc[1][nb2 * 2 + 1], pf[1], vr[2], vr[3]);
            }
        }
        // no trailing sync: next iteration's top sync is the WAR fence
    }

    // finalize rowsums across the quad and write out
    #pragma unroll
    for (int mg = 0; mg < 2; mg++) {
        float r0s = rs[mg][0], r1s = rs[mg][1];
        r0s += __shfl_xor_sync(0xffffffffu, r0s, 1);
        r0s += __shfl_xor_sync(0xffffffffu, r0s, 2);
        r1s += __shfl_xor_sync(0xffffffffu, r1s, 1);
        r1s += __shfl_xor_sync(0xffffffffu, r1s, 2);
        const float inv0 = 1.0f / r0s, inv1 = 1.0f / r1s;

        const int row0 = st * 128 + m0 + mg * 16 + (lane >> 2);
        const int c0   = (lane & 3) * 2;
        #pragma unroll
        for (int nb = 0; nb < 8; nb++) {
            float2 v0 = make_float2(oacc[mg][nb][0] * inv0, oacc[mg][nb][1] * inv0);
            float2 v1 = make_float2(oacc[mg][nb][2] * inv1, oacc[mg][nb][3] * inv1);
            size_t base0 = ((size_t)(b * S_ + row0) * D_) + h * HD_ + nb * 8 + c0;
            size_t base1 = ((size_t)(b * S_ + row0 + 8) * D_) + h * HD_ + nb * 8 + c0;
            *(float2*)(Out + base0) = v0;
            *(float2*)(Out + base1) = v1;
        }
    }
}

// ---------------------------------------------------------------------------
// Launch
// ---------------------------------------------------------------------------
extern "C" void kernel_launch(void* const* d_in, const int* in_sizes, int n_in,
                              void* d_out, int out_size)
{
    const float* H  = (const float*)d_in[0];  // [8,512,1024]
    const float* Wq = (const float*)d_in[1];  // [1024,1024]
    const float* K  = (const float*)d_in[2];  // [8,16,2048,64]
    const float* V  = (const float*)d_in[3];  // [8,16,2048,64]
    const float* M  = (const float*)d_in[4];  // [8,2048]
    float* out = (float*)d_out;               // [8,512,1024]

    __nv_bfloat16 *kb, *vb, *hb, *wb;
    cudaGetSymbolAddress((void**)&kb, d_kbf);
    cudaGetSymbolAddress((void**)&vb, d_vbf);
    cudaGetSymbolAddress((void**)&hb, d_hbf);
    cudaGetSymbolAddress((void**)&wb, d_wbf);

    const int nKV4 = (B_ * NH_ * KV_ * HD_) / 4;   // 4,194,304
    const int nH4  = (B_ * S_ * D_) / 4;           // 1,048,576
    const int nW4  = (D_ * D_) / 4;                // 262,144

    cvt_kernel<<<(nKV4 + 255) / 256, 256>>>((const float4*)K, (float2*)kb, nKV4);
    cvt_kernel<<<(nKV4 + 255) / 256, 256>>>((const float4*)V, (float2*)vb, nKV4);
    cvt_kernel<<<(nH4 + 255) / 256, 256>>>((const float4*)H, (float2*)hb, nH4);
    cvt_kernel<<<(nW4 + 255) / 256, 256>>>((const float4*)Wq, (float2*)wb, nW4);

    qproj_kernel<<<dim3(8, 32), 256>>>();
    attn_kernel<<<dim3(4, 16, 8), 128>>>(M, out);
}

// round 13
// speedup vs baseline: 1.0889x; 1.0836x over previous
#include <cuda_runtime.h>
#include <cuda_bf16.h>
#include <mma.h>
#include <cstdint>

using namespace nvcuda;

#define B_  8
#define S_  512
#define KV_ 2048
#define NH_ 16
#define HD_ 64
#define D_  1024

// bf16 scratch buffers
__device__ __nv_bfloat16 d_kbf[(size_t)B_ * NH_ * KV_ * HD_];     // [bh][kv][d]
__device__ __nv_bfloat16 d_vbf[(size_t)B_ * NH_ * KV_ * HD_];     // [bh][kv][d]
__device__ __nv_bfloat16 d_hbf[(size_t)B_ * S_ * D_];
__device__ __nv_bfloat16 d_wbf[(size_t)D_ * D_];
__device__ __nv_bfloat16 d_qscratch[(size_t)B_ * NH_ * S_ * HD_]; // [bh][s][d]

// ---------------------------------------------------------------------------
// PTX helpers
// ---------------------------------------------------------------------------
__device__ __forceinline__ void ldsm4(uint32_t* r, uint32_t a) {
    asm volatile("ldmatrix.sync.aligned.m8n8.x4.shared.b16 {%0,%1,%2,%3}, [%4];\n"
        : "=r"(r[0]), "=r"(r[1]), "=r"(r[2]), "=r"(r[3]) : "r"(a));
}
__device__ __forceinline__ void ldsm4t(uint32_t* r, uint32_t a) {
    asm volatile("ldmatrix.sync.aligned.m8n8.x4.trans.shared.b16 {%0,%1,%2,%3}, [%4];\n"
        : "=r"(r[0]), "=r"(r[1]), "=r"(r[2]), "=r"(r[3]) : "r"(a));
}
__device__ __forceinline__ void mma16816(float* c, const uint32_t* a, uint32_t b0, uint32_t b1) {
    asm volatile("mma.sync.aligned.m16n8k16.row.col.f32.bf16.bf16.f32 "
        "{%0,%1,%2,%3}, {%4,%5,%6,%7}, {%8,%9}, {%0,%1,%2,%3};\n"
        : "+f"(c[0]), "+f"(c[1]), "+f"(c[2]), "+f"(c[3])
        : "r"(a[0]), "r"(a[1]), "r"(a[2]), "r"(a[3]), "r"(b0), "r"(b1));
}
#define CP16(dst, src) asm volatile("cp.async.cg.shared.global [%0], [%1], 16;\n" :: "r"(dst), "l"(src))
#define CP_COMMIT()    asm volatile("cp.async.commit_group;\n")
#define CP_WAIT0()     asm volatile("cp.async.wait_group 0;\n")

__device__ __forceinline__ uint32_t pack_bf2(float a, float b) {
    __nv_bfloat162 t = __float22bfloat162_rn(make_float2(a, b));
    return *(uint32_t*)&t;
}
#define SWZ128(x) ((x) ^ (((x) >> 3) & 0x70))

// ---------------------------------------------------------------------------
// fp32 -> bf16 conversion, MLP=4: each block converts 1024 float4s, each
// thread issues 4 independent coalesced loads. n4 must be a multiple of 1024
// (true for all four arrays here), so no bounds checks.
// ---------------------------------------------------------------------------
__global__ __launch_bounds__(256)
void cvt_kernel(const float4* __restrict__ src, float2* __restrict__ dst, int n4)
{
    const int i0 = blockIdx.x * 1024 + threadIdx.x;
    float4 v0 = src[i0];
    float4 v1 = src[i0 + 256];
    float4 v2 = src[i0 + 512];
    float4 v3 = src[i0 + 768];

    __nv_bfloat162 o0[2], o1[2], o2[2], o3[2];
    o0[0] = __float22bfloat162_rn(make_float2(v0.x, v0.y));
    o0[1] = __float22bfloat162_rn(make_float2(v0.z, v0.w));
    o1[0] = __float22bfloat162_rn(make_float2(v1.x, v1.y));
    o1[1] = __float22bfloat162_rn(make_float2(v1.z, v1.w));
    o2[0] = __float22bfloat162_rn(make_float2(v2.x, v2.y));
    o2[1] = __float22bfloat162_rn(make_float2(v2.z, v2.w));
    o3[0] = __float22bfloat162_rn(make_float2(v3.x, v3.y));
    o3[1] = __float22bfloat162_rn(make_float2(v3.z, v3.w));

    dst[i0]       = *(float2*)o0;
    dst[i0 + 256] = *(float2*)o1;
    dst[i0 + 512] = *(float2*)o2;
    dst[i0 + 768] = *(float2*)o3;
}

// ---------------------------------------------------------------------------
// Q projection — byte-identical to R8 (known-good)
// ---------------------------------------------------------------------------
__global__ __launch_bounds__(256)
void qproj_kernel()
{
    __shared__ __align__(16) char smem_raw[2 * 128 * 72 * 2];
    __nv_bfloat16* As = (__nv_bfloat16*)smem_raw;
    __nv_bfloat16* Bs = As + 128 * 72;
    float* Cs = (float*)smem_raw;

    const int n0 = blockIdx.x * 128;
    const int m0 = blockIdx.y * 128;
    const int tid = threadIdx.x;
    const int wid = tid >> 5;
    const int wr = wid & 3;
    const int wc = wid >> 2;

    wmma::fragment<wmma::accumulator, 16, 16, 16, float> acc[2][4];
    #pragma unroll
    for (int i = 0; i < 2; i++)
        #pragma unroll
        for (int j = 0; j < 4; j++) wmma::fill_fragment(acc[i][j], 0.0f);

    for (int kt = 0; kt < 16; kt++) {
        const int k0 = kt * 64;
        for (int i = tid; i < 128 * 8; i += 256) {
            int r = i >> 3, c = (i & 7) * 8;
            *(uint4*)&As[r * 72 + c] = *(const uint4*)(d_hbf + (size_t)(m0 + r) * D_ + k0 + c);
            *(uint4*)&Bs[r * 72 + c] = *(const uint4*)(d_wbf + (size_t)(n0 + r) * D_ + k0 + c);
        }
        __syncthreads();
        #pragma unroll
        for (int ks = 0; ks < 4; ks++) {
            wmma::fragment<wmma::matrix_a, 16, 16, 16, __nv_bfloat16, wmma::row_major> af[2];
            wmma::load_matrix_sync(af[0], &As[(wr * 32 + 0)  * 72 + ks * 16], 72);
            wmma::load_matrix_sync(af[1], &As[(wr * 32 + 16) * 72 + ks * 16], 72);
            #pragma unroll
            for (int j = 0; j < 4; j++) {
                wmma::fragment<wmma::matrix_b, 16, 16, 16, __nv_bfloat16, wmma::col_major> bf;
                wmma::load_matrix_sync(bf, &Bs[(wc * 64 + j * 16) * 72 + ks * 16], 72);
                wmma::mma_sync(acc[0][j], af[0], bf, acc[0][j]);
                wmma::mma_sync(acc[1][j], af[1], bf, acc[1][j]);
            }
        }
        __syncthreads();
    }

    #pragma unroll
    for (int half = 0; half < 2; half++) {
        __syncthreads();
        if ((wr >> 1) == half) {
            const int lr = (wr & 1) * 32;
            #pragma unroll
            for (int i = 0; i < 2; i++)
                #pragma unroll
                for (int j = 0; j < 4; j++)
                    wmma::store_matrix_sync(&Cs[(lr + i * 16) * 132 + wc * 64 + j * 16],
                                            acc[i][j], 132, wmma::mem_row_major);
        }
        __syncthreads();
        for (int i = tid; i < 64 * 16; i += 256) {
            int r = i >> 4, c8 = (i & 15) * 8;
            int gm = m0 + half * 64 + r;
            int gn = n0 + c8;
            int b = gm >> 9, s = gm & 511;
            int h = gn >> 6, d = gn & 63;
            const float* src = &Cs[r * 132 + c8];
            __nv_bfloat162 o[4];
            o[0] = __float22bfloat162_rn(make_float2(src[0], src[1]));
            o[1] = __float22bfloat162_rn(make_float2(src[2], src[3]));
            o[2] = __float22bfloat162_rn(make_float2(src[4], src[5]));
            o[3] = __float22bfloat162_rn(make_float2(src[6], src[7]));
            *(uint4*)(d_qscratch + (((size_t)(b * NH_ + h) * S_ + s) * HD_ + d)) = *(uint4*)o;
        }
    }
}

// ---------------------------------------------------------------------------
// Fused flash attention — byte-identical to the R8 passing kernel.
// CTA = 64 queries (4 warps x 16 rows), 128 threads, KV tiles of 64.
// Per tile, two 32-kv halves: S-mma -> {exp chunk, PV chunk} interleaved.
// smem: K[2][8KB] + V[2][8KB] + M[2][256B] = 33.3 KB -> 5 CTAs/SM.
// grid (8 s-tiles, 16 heads, 8 batch).
// ---------------------------------------------------------------------------
#define NT (KV_ / 64)

__global__ __launch_bounds__(128, 5)
void attn_kernel(const float* __restrict__ Mg_, float* __restrict__ Out)
{
    __shared__ __align__(1024) __nv_bfloat16 sK[2][64 * 64];
    __shared__ __align__(1024) __nv_bfloat16 sV[2][64 * 64];
    __shared__ __align__(16)   float         sM[2][64];

    const int st = blockIdx.x, h = blockIdx.y, b = blockIdx.z;
    const size_t bh = (size_t)b * NH_ + h;
    const __nv_bfloat16* Kh = d_kbf + bh * KV_ * HD_;
    const __nv_bfloat16* Vh = d_vbf + bh * KV_ * HD_;
    const float* Mg = Mg_ + (size_t)b * KV_;

    const int tid = threadIdx.x;
    const int wid = tid >> 5;
    const int lane = tid & 31;

    const uint32_t ks_b = (uint32_t)__cvta_generic_to_shared(sK[0]);
    const uint32_t vs_b = (uint32_t)__cvta_generic_to_shared(sV[0]);
    const uint32_t ms_b = (uint32_t)__cvta_generic_to_shared(sM[0]);

    // one KV tile (K + V + mask) -> swizzled buffer `buf`, one commit group
    auto load_tile = [&](int buf, int kv0) {
        #pragma unroll
        for (int i = 0; i < 4; i++) {
            int idx = tid + i * 128;                 // 512 chunks of 16B
            int r = idx >> 3, c16 = (idx & 7) * 16;
            uint32_t off = (uint32_t)(buf * 8192) + SWZ128((uint32_t)(r * 128 + c16));
            CP16(ks_b + off, Kh + (size_t)(kv0 + r) * HD_ + c16 / 2);
            CP16(vs_b + off, Vh + (size_t)(kv0 + r) * HD_ + c16 / 2);
        }
        if (tid < 16) CP16(ms_b + (uint32_t)(buf * 256 + tid * 16), Mg + kv0 + tid * 4);
    };

    load_tile(0, 0);
    CP_COMMIT();      // group 0

    // Q fragments loaded directly from gmem in the standard mma A-layout
    const int m0 = wid * 16;
    const __nv_bfloat16* Qg = d_qscratch + (bh * S_ + st * 64) * HD_;
    uint32_t qf[4][4];
    {
        const int r0 = m0 + (lane >> 2);
        const int cb = (lane & 3) * 2;
        #pragma unroll
        for (int kb = 0; kb < 4; kb++) {
            qf[kb][0] = *(const uint32_t*)(Qg + (size_t)r0 * HD_ + kb * 16 + cb);
            qf[kb][1] = *(const uint32_t*)(Qg + (size_t)(r0 + 8) * HD_ + kb * 16 + cb);
            qf[kb][2] = *(const uint32_t*)(Qg + (size_t)r0 * HD_ + kb * 16 + cb + 8);
            qf[kb][3] = *(const uint32_t*)(Qg + (size_t)(r0 + 8) * HD_ + kb * 16 + cb + 8);
        }
    }

    float oacc[8][4];
    #pragma unroll
    for (int i = 0; i < 8; i++)
        #pragma unroll
        for (int j = 0; j < 4; j++) oacc[i][j] = 0.0f;
    float rs0 = 0.0f, rs1 = 0.0f;

    // lane-derived ldsm address components
    const int lrow = (lane & 7) + ((lane >> 3) & 1) * 8;   // row within 16-chunk
    const int lcolb = ((lane >> 4) & 1) * 16;              // byte col within 32B

    for (int t = 0; t < NT; t++) {
        const int cur = t & 1;
        const uint32_t kbase = ks_b + (uint32_t)cur * 8192;
        const uint32_t vbase = vs_b + (uint32_t)cur * 8192;
        const float* mrow = sM[cur];

        CP_WAIT0();        // tile t resident
        __syncthreads();   // visible to all warps; WAR fence for buf^1

        if (t + 1 < NT) load_tile(cur ^ 1, (t + 1) * 64);
        CP_COMMIT();

        #pragma unroll
        for (int hv = 0; hv < 2; hv++) {       // two 32-kv halves
            // ---- S = Q K^T for kv cols [hv*32, hv*32+32) ----
            float sacc[4][4];
            #pragma unroll
            for (int i = 0; i < 4; i++)
                #pragma unroll
                for (int j = 0; j < 4; j++) sacc[i][j] = 0.0f;

            #pragma unroll
            for (int kb = 0; kb < 4; kb++) {
                #pragma unroll
                for (int nb2 = 0; nb2 < 2; nb2++) {
                    uint32_t kr[4];
                    int row = hv * 32 + nb2 * 16 + lrow;
                    int colb = kb * 32 + lcolb;
                    ldsm4(kr, kbase + SWZ128((uint32_t)(row * 128 + colb)));
                    mma16816(sacc[nb2 * 2 + 0], qf[kb], kr[0], kr[2]);
                    mma16816(sacc[nb2 * 2 + 1], qf[kb], kr[1], kr[3]);
                }
            }

            // ---- exp + PV interleaved per 16-kv chunk ----
            #pragma unroll
            for (int kvc = 0; kvc < 2; kvc++) {
                uint32_t pf[4];
                #pragma unroll
                for (int hh = 0; hh < 2; hh++) {
                    const int nb = kvc * 2 + hh;
                    const int c0 = hv * 32 + nb * 8 + (lane & 3) * 2;
                    float mv0 = mrow[c0], mv1 = mrow[c0 + 1];
                    float p0 = __expf(sacc[nb][0] + mv0);
                    float p1 = __expf(sacc[nb][1] + mv1);
                    float p2 = __expf(sacc[nb][2] + mv0);
                    float p3 = __expf(sacc[nb][3] + mv1);
                    rs0 += p0 + p1;
                    rs1 += p2 + p3;
                    pf[hh * 2 + 0] = pack_bf2(p0, p1);
                    pf[hh * 2 + 1] = pack_bf2(p2, p3);
                }
                #pragma unroll
                for (int nb2 = 0; nb2 < 4; nb2++) {
                    uint32_t vr[4];
                    int vrow = hv * 32 + kvc * 16 + lrow;
                    int vcolb = nb2 * 32 + lcolb;
                    ldsm4t(vr, vbase + SWZ128((uint32_t)(vrow * 128 + vcolb)));
                    mma16816(oacc[nb2 * 2 + 0], pf, vr[0], vr[1]);
                    mma16816(oacc[nb2 * 2 + 1], pf, vr[2], vr[3]);
                }
            }
        }
        // no trailing sync: next iteration's top sync is the WAR fence
    }

    // finalize rowsums across the quad (cols are spread over lane%4)
    rs0 += __shfl_xor_sync(0xffffffffu, rs0, 1);
    rs0 += __shfl_xor_sync(0xffffffffu, rs0, 2);
    rs1 += __shfl_xor_sync(0xffffffffu, rs1, 1);
    rs1 += __shfl_xor_sync(0xffffffffu, rs1, 2);
    const float inv0 = 1.0f / rs0, inv1 = 1.0f / rs1;

    const int row0 = st * 64 + m0 + (lane >> 2);
    const int c0   = (lane & 3) * 2;
    #pragma unroll
    for (int nb = 0; nb < 8; nb++) {
        float2 v0 = make_float2(oacc[nb][0] * inv0, oacc[nb][1] * inv0);
        float2 v1 = make_float2(oacc[nb][2] * inv1, oacc[nb][3] * inv1);
        size_t base0 = ((size_t)(b * S_ + row0) * D_) + h * HD_ + nb * 8 + c0;
        size_t base1 = ((size_t)(b * S_ + row0 + 8) * D_) + h * HD_ + nb * 8 + c0;
        *(float2*)(Out + base0) = v0;
        *(float2*)(Out + base1) = v1;
    }
}

// ---------------------------------------------------------------------------
// Launch — same structure as R8 (4 cvt launches, qproj, attn)
// ---------------------------------------------------------------------------
extern "C" void kernel_launch(void* const* d_in, const int* in_sizes, int n_in,
                              void* d_out, int out_size)
{
    const float* H  = (const float*)d_in[0];  // [8,512,1024]
    const float* Wq = (const float*)d_in[1];  // [1024,1024]
    const float* K  = (const float*)d_in[2];  // [8,16,2048,64]
    const float* V  = (const float*)d_in[3];  // [8,16,2048,64]
    const float* M  = (const float*)d_in[4];  // [8,2048]
    float* out = (float*)d_out;               // [8,512,1024]

    __nv_bfloat16 *kb, *vb, *hb, *wb;
    cudaGetSymbolAddress((void**)&kb, d_kbf);
    cudaGetSymbolAddress((void**)&vb, d_vbf);
    cudaGetSymbolAddress((void**)&hb, d_hbf);
    cudaGetSymbolAddress((void**)&wb, d_wbf);

    const int nKV4 = (B_ * NH_ * KV_ * HD_) / 4;   // 4,194,304
    const int nH4  = (B_ * S_ * D_) / 4;           // 1,048,576
    const int nW4  = (D_ * D_) / 4;                // 262,144

    cvt_kernel<<<nKV4 / 1024, 256>>>((const float4*)K, (float2*)kb, nKV4);
    cvt_kernel<<<nKV4 / 1024, 256>>>((const float4*)V, (float2*)vb, nKV4);
    cvt_kernel<<<nH4 / 1024, 256>>>((const float4*)H, (float2*)hb, nH4);
    cvt_kernel<<<nW4 / 1024, 256>>>((const float4*)Wq, (float2*)wb, nW4);

    qproj_kernel<<<dim3(8, 32), 256>>>();
    attn_kernel<<<dim3(8, 16, 8), 128>>>(M, out);
}

// round 14
// speedup vs baseline: 1.0962x; 1.0067x over previous
#include <cuda_runtime.h>
#include <cuda_bf16.h>
#include <mma.h>
#include <cstdint>

using namespace nvcuda;

#define B_  8
#define S_  512
#define KV_ 2048
#define NH_ 16
#define HD_ 64
#define D_  1024

// bf16 scratch buffers
__device__ __nv_bfloat16 d_kbf[(size_t)B_ * NH_ * KV_ * HD_];     // [bh][kv][d]
__device__ __nv_bfloat16 d_vbf[(size_t)B_ * NH_ * KV_ * HD_];     // [bh][kv][d]
__device__ __nv_bfloat16 d_hbf[(size_t)B_ * S_ * D_];
__device__ __nv_bfloat16 d_wbf[(size_t)D_ * D_];
__device__ __nv_bfloat16 d_qscratch[(size_t)B_ * NH_ * S_ * HD_]; // [bh][s][d]

// ---------------------------------------------------------------------------
// PTX helpers
// ---------------------------------------------------------------------------
__device__ __forceinline__ void ldsm4(uint32_t* r, uint32_t a) {
    asm volatile("ldmatrix.sync.aligned.m8n8.x4.shared.b16 {%0,%1,%2,%3}, [%4];\n"
        : "=r"(r[0]), "=r"(r[1]), "=r"(r[2]), "=r"(r[3]) : "r"(a));
}
__device__ __forceinline__ void ldsm4t(uint32_t* r, uint32_t a) {
    asm volatile("ldmatrix.sync.aligned.m8n8.x4.trans.shared.b16 {%0,%1,%2,%3}, [%4];\n"
        : "=r"(r[0]), "=r"(r[1]), "=r"(r[2]), "=r"(r[3]) : "r"(a));
}
__device__ __forceinline__ void mma16816(float* c, const uint32_t* a, uint32_t b0, uint32_t b1) {
    asm volatile("mma.sync.aligned.m16n8k16.row.col.f32.bf16.bf16.f32 "
        "{%0,%1,%2,%3}, {%4,%5,%6,%7}, {%8,%9}, {%0,%1,%2,%3};\n"
        : "+f"(c[0]), "+f"(c[1]), "+f"(c[2]), "+f"(c[3])
        : "r"(a[0]), "r"(a[1]), "r"(a[2]), "r"(a[3]), "r"(b0), "r"(b1));
}
#define CP16(dst, src) asm volatile("cp.async.cg.shared.global [%0], [%1], 16;\n" :: "r"(dst), "l"(src))
#define CP_COMMIT()    asm volatile("cp.async.commit_group;\n")
#define CP_WAIT0()     asm volatile("cp.async.wait_group 0;\n")

__device__ __forceinline__ uint32_t pack_bf2(float a, float b) {
    __nv_bfloat162 t = __float22bfloat162_rn(make_float2(a, b));
    return *(uint32_t*)&t;
}
#define SWZ128(x) ((x) ^ (((x) >> 3) & 0x70))

// ---------------------------------------------------------------------------
// fp32 -> bf16 conversion, MLP=4 (byte-identical to R13 passing kernel)
// ---------------------------------------------------------------------------
__global__ __launch_bounds__(256)
void cvt_kernel(const float4* __restrict__ src, float2* __restrict__ dst, int n4)
{
    const int i0 = blockIdx.x * 1024 + threadIdx.x;
    float4 v0 = src[i0];
    float4 v1 = src[i0 + 256];
    float4 v2 = src[i0 + 512];
    float4 v3 = src[i0 + 768];

    __nv_bfloat162 o0[2], o1[2], o2[2], o3[2];
    o0[0] = __float22bfloat162_rn(make_float2(v0.x, v0.y));
    o0[1] = __float22bfloat162_rn(make_float2(v0.z, v0.w));
    o1[0] = __float22bfloat162_rn(make_float2(v1.x, v1.y));
    o1[1] = __float22bfloat162_rn(make_float2(v1.z, v1.w));
    o2[0] = __float22bfloat162_rn(make_float2(v2.x, v2.y));
    o2[1] = __float22bfloat162_rn(make_float2(v2.z, v2.w));
    o3[0] = __float22bfloat162_rn(make_float2(v3.x, v3.y));
    o3[1] = __float22bfloat162_rn(make_float2(v3.z, v3.w));

    dst[i0]       = *(float2*)o0;
    dst[i0 + 256] = *(float2*)o1;
    dst[i0 + 512] = *(float2*)o2;
    dst[i0 + 768] = *(float2*)o3;
}

// ---------------------------------------------------------------------------
// Q projection — byte-identical to R13 (known-good)
// ---------------------------------------------------------------------------
__global__ __launch_bounds__(256)
void qproj_kernel()
{
    __shared__ __align__(16) char smem_raw[2 * 128 * 72 * 2];
    __nv_bfloat16* As = (__nv_bfloat16*)smem_raw;
    __nv_bfloat16* Bs = As + 128 * 72;
    float* Cs = (float*)smem_raw;

    const int n0 = blockIdx.x * 128;
    const int m0 = blockIdx.y * 128;
    const int tid = threadIdx.x;
    const int wid = tid >> 5;
    const int wr = wid & 3;
    const int wc = wid >> 2;

    wmma::fragment<wmma::accumulator, 16, 16, 16, float> acc[2][4];
    #pragma unroll
    for (int i = 0; i < 2; i++)
        #pragma unroll
        for (int j = 0; j < 4; j++) wmma::fill_fragment(acc[i][j], 0.0f);

    for (int kt = 0; kt < 16; kt++) {
        const int k0 = kt * 64;
        for (int i = tid; i < 128 * 8; i += 256) {
            int r = i >> 3, c = (i & 7) * 8;
            *(uint4*)&As[r * 72 + c] = *(const uint4*)(d_hbf + (size_t)(m0 + r) * D_ + k0 + c);
            *(uint4*)&Bs[r * 72 + c] = *(const uint4*)(d_wbf + (size_t)(n0 + r) * D_ + k0 + c);
        }
        __syncthreads();
        #pragma unroll
        for (int ks = 0; ks < 4; ks++) {
            wmma::fragment<wmma::matrix_a, 16, 16, 16, __nv_bfloat16, wmma::row_major> af[2];
            wmma::load_matrix_sync(af[0], &As[(wr * 32 + 0)  * 72 + ks * 16], 72);
            wmma::load_matrix_sync(af[1], &As[(wr * 32 + 16) * 72 + ks * 16], 72);
            #pragma unroll
            for (int j = 0; j < 4; j++) {
                wmma::fragment<wmma::matrix_b, 16, 16, 16, __nv_bfloat16, wmma::col_major> bf;
                wmma::load_matrix_sync(bf, &Bs[(wc * 64 + j * 16) * 72 + ks * 16], 72);
                wmma::mma_sync(acc[0][j], af[0], bf, acc[0][j]);
                wmma::mma_sync(acc[1][j], af[1], bf, acc[1][j]);
            }
        }
        __syncthreads();
    }

    #pragma unroll
    for (int half = 0; half < 2; half++) {
        __syncthreads();
        if ((wr >> 1) == half) {
            const int lr = (wr & 1) * 32;
            #pragma unroll
            for (int i = 0; i < 2; i++)
                #pragma unroll
                for (int j = 0; j < 4; j++)
                    wmma::store_matrix_sync(&Cs[(lr + i * 16) * 132 + wc * 64 + j * 16],
                                            acc[i][j], 132, wmma::mem_row_major);
        }
        __syncthreads();
        for (int i = tid; i < 64 * 16; i += 256) {
            int r = i >> 4, c8 = (i & 15) * 8;
            int gm = m0 + half * 64 + r;
            int gn = n0 + c8;
            int b = gm >> 9, s = gm & 511;
            int h = gn >> 6, d = gn & 63;
            const float* src = &Cs[r * 132 + c8];
            __nv_bfloat162 o[4];
            o[0] = __float22bfloat162_rn(make_float2(src[0], src[1]));
            o[1] = __float22bfloat162_rn(make_float2(src[2], src[3]));
            o[2] = __float22bfloat162_rn(make_float2(src[4], src[5]));
            o[3] = __float22bfloat162_rn(make_float2(src[6], src[7]));
            *(uint4*)(d_qscratch + (((size_t)(b * NH_ + h) * S_ + s) * HD_ + d)) = *(uint4*)o;
        }
    }
}

// ---------------------------------------------------------------------------
// Fused flash attention — R8 shape (64q/CTA, 4 warps x 16 rows, 5 CTAs/SM)
// with software-pipelined kv-16 chunks: S-mma(c+1) issued before
// exp(c)/PV(c), giving the MUFU burst independent tensor work to overlap.
// grid (8 s-tiles, 16 heads, 8 batch), 128 threads.
// ---------------------------------------------------------------------------
#define NT (KV_ / 64)

__global__ __launch_bounds__(128, 5)
void attn_kernel(const float* __restrict__ Mg_, float* __restrict__ Out)
{
    __shared__ __align__(1024) __nv_bfloat16 sK[2][64 * 64];
    __shared__ __align__(1024) __nv_bfloat16 sV[2][64 * 64];
    __shared__ __align__(16)   float         sM[2][64];

    const int st = blockIdx.x, h = blockIdx.y, b = blockIdx.z;
    const size_t bh = (size_t)b * NH_ + h;
    const __nv_bfloat16* Kh = d_kbf + bh * KV_ * HD_;
    const __nv_bfloat16* Vh = d_vbf + bh * KV_ * HD_;
    const float* Mg = Mg_ + (size_t)b * KV_;

    const int tid = threadIdx.x;
    const int wid = tid >> 5;
    const int lane = tid & 31;

    const uint32_t ks_b = (uint32_t)__cvta_generic_to_shared(sK[0]);
    const uint32_t vs_b = (uint32_t)__cvta_generic_to_shared(sV[0]);
    const uint32_t ms_b = (uint32_t)__cvta_generic_to_shared(sM[0]);

    // one KV tile (K + V + mask) -> swizzled buffer `buf`, one commit group
    auto load_tile = [&](int buf, int kv0) {
        #pragma unroll
        for (int i = 0; i < 4; i++) {
            int idx = tid + i * 128;                 // 512 chunks of 16B
            int r = idx >> 3, c16 = (idx & 7) * 16;
            uint32_t off = (uint32_t)(buf * 8192) + SWZ128((uint32_t)(r * 128 + c16));
            CP16(ks_b + off, Kh + (size_t)(kv0 + r) * HD_ + c16 / 2);
            CP16(vs_b + off, Vh + (size_t)(kv0 + r) * HD_ + c16 / 2);
        }
        if (tid < 16) CP16(ms_b + (uint32_t)(buf * 256 + tid * 16), Mg + kv0 + tid * 4);
    };

    load_tile(0, 0);
    CP_COMMIT();      // group 0

    // Q fragments loaded directly from gmem in the standard mma A-layout
    const int m0 = wid * 16;
    const __nv_bfloat16* Qg = d_qscratch + (bh * S_ + st * 64) * HD_;
    uint32_t qf[4][4];
    {
        const int r0 = m0 + (lane >> 2);
        const int cb = (lane & 3) * 2;
        #pragma unroll
        for (int kb = 0; kb < 4; kb++) {
            qf[kb][0] = *(const uint32_t*)(Qg + (size_t)r0 * HD_ + kb * 16 + cb);
            qf[kb][1] = *(const uint32_t*)(Qg + (size_t)(r0 + 8) * HD_ + kb * 16 + cb);
            qf[kb][2] = *(const uint32_t*)(Qg + (size_t)r0 * HD_ + kb * 16 + cb + 8);
            qf[kb][3] = *(const uint32_t*)(Qg + (size_t)(r0 + 8) * HD_ + kb * 16 + cb + 8);
        }
    }

    float oacc[8][4];
    #pragma unroll
    for (int i = 0; i < 8; i++)
        #pragma unroll
        for (int j = 0; j < 4; j++) oacc[i][j] = 0.0f;
    float rs0 = 0.0f, rs1 = 0.0f;

    // lane-derived ldsm address components
    const int lrow = (lane & 7) + ((lane >> 3) & 1) * 8;   // row within 16-chunk
    const int lcolb = ((lane >> 4) & 1) * 16;              // byte col within 32B

    for (int t = 0; t < NT; t++) {
        const int cur = t & 1;
        const uint32_t kbase = ks_b + (uint32_t)cur * 8192;
        const uint32_t vbase = vs_b + (uint32_t)cur * 8192;
        const float* mrow = sM[cur];

        CP_WAIT0();        // tile t resident
        __syncthreads();   // visible to all warps; WAR fence for buf^1

        if (t + 1 < NT) load_tile(cur ^ 1, (t + 1) * 64);
        CP_COMMIT();

        // S-mma for one kv-16 chunk -> 8 accumulator regs
        auto qk_chunk = [&](int c, float (*sacc)[4]) {
            #pragma unroll
            for (int i = 0; i < 2; i++)
                #pragma unroll
                for (int j = 0; j < 4; j++) sacc[i][j] = 0.0f;
            const int row = c * 16 + lrow;
            #pragma unroll
            for (int kb = 0; kb < 4; kb++) {
                uint32_t kr[4];
                ldsm4(kr, kbase + SWZ128((uint32_t)(row * 128 + kb * 32 + lcolb)));
                mma16816(sacc[0], qf[kb], kr[0], kr[2]);
                mma16816(sacc[1], qf[kb], kr[1], kr[3]);
            }
        };
        // exp + PV for one chunk
        auto exp_pv_chunk = [&](int c, float (*sacc)[4]) {
            uint32_t pf[4];
            #pragma unroll
            for (int ng = 0; ng < 2; ng++) {
                const int c0 = c * 16 + ng * 8 + (lane & 3) * 2;
                float mv0 = mrow[c0], mv1 = mrow[c0 + 1];
                float p0 = __expf(sacc[ng][0] + mv0);
                float p1 = __expf(sacc[ng][1] + mv1);
                float p2 = __expf(sacc[ng][2] + mv0);
                float p3 = __expf(sacc[ng][3] + mv1);
                rs0 += p0 + p1;
                rs1 += p2 + p3;
                pf[ng * 2 + 0] = pack_bf2(p0, p1);
                pf[ng * 2 + 1] = pack_bf2(p2, p3);
            }
            const int vrow = c * 16 + lrow;
            #pragma unroll
            for (int nb2 = 0; nb2 < 4; nb2++) {
                uint32_t vr[4];
                ldsm4t(vr, vbase + SWZ128((uint32_t)(vrow * 128 + nb2 * 32 + lcolb)));
                mma16816(oacc[nb2 * 2 + 0], pf, vr[0], vr[1]);
                mma16816(oacc[nb2 * 2 + 1], pf, vr[2], vr[3]);
            }
        };

        // software pipeline: S(c+1) issued before exp(c)/PV(c)
        float sA[2][4], sB[2][4];
        qk_chunk(0, sA);
        qk_chunk(1, sB);
        exp_pv_chunk(0, sA);
        qk_chunk(2, sA);
        exp_pv_chunk(1, sB);
        qk_chunk(3, sB);
        exp_pv_chunk(2, sA);
        exp_pv_chunk(3, sB);
        // no trailing sync: next iteration's top sync is the WAR fence
    }

    // finalize rowsums across the quad
    rs0 += __shfl_xor_sync(0xffffffffu, rs0, 1);
    rs0 += __shfl_xor_sync(0xffffffffu, rs0, 2);
    rs1 += __shfl_xor_sync(0xffffffffu, rs1, 1);
    rs1 += __shfl_xor_sync(0xffffffffu, rs1, 2);
    const float inv0 = 1.0f / rs0, inv1 = 1.0f / rs1;

    const int row0 = st * 64 + m0 + (lane >> 2);
    const int c0   = (lane & 3) * 2;
    #pragma unroll
    for (int nb = 0; nb < 8; nb++) {
        float2 v0 = make_float2(oacc[nb][0] * inv0, oacc[nb][1] * inv0);
        float2 v1 = make_float2(oacc[nb][2] * inv1, oacc[nb][3] * inv1);
        size_t base0 = ((size_t)(b * S_ + row0) * D_) + h * HD_ + nb * 8 + c0;
        size_t base1 = ((size_t)(b * S_ + row0 + 8) * D_) + h * HD_ + nb * 8 + c0;
        *(float2*)(Out + base0) = v0;
        *(float2*)(Out + base1) = v1;
    }
}

// ---------------------------------------------------------------------------
// Launch — same structure as R13 (4 cvt launches, qproj, attn)
// ---------------------------------------------------------------------------
extern "C" void kernel_launch(void* const* d_in, const int* in_sizes, int n_in,
                              void* d_out, int out_size)
{
    const float* H  = (const float*)d_in[0];  // [8,512,1024]
    const float* Wq = (const float*)d_in[1];  // [1024,1024]
    const float* K  = (const float*)d_in[2];  // [8,16,2048,64]
    const float* V  = (const float*)d_in[3];  // [8,16,2048,64]
    const float* M  = (const float*)d_in[4];  // [8,2048]
    float* out = (float*)d_out;               // [8,512,1024]

    __nv_bfloat16 *kb, *vb, *hb, *wb;
    cudaGetSymbolAddress((void**)&kb, d_kbf);
    cudaGetSymbolAddress((void**)&vb, d_vbf);
    cudaGetSymbolAddress((void**)&hb, d_hbf);
    cudaGetSymbolAddress((void**)&wb, d_wbf);

    const int nKV4 = (B_ * NH_ * KV_ * HD_) / 4;   // 4,194,304
    const int nH4  = (B_ * S_ * D_) / 4;           // 1,048,576
    const int nW4  = (D_ * D_) / 4;                // 262,144

    cvt_kernel<<<nKV4 / 1024, 256>>>((const float4*)K, (float2*)kb, nKV4);
    cvt_kernel<<<nKV4 / 1024, 256>>>((const float4*)V, (float2*)vb, nKV4);
    cvt_kernel<<<nH4 / 1024, 256>>>((const float4*)H, (float2*)hb, nH4);
    cvt_kernel<<<nW4 / 1024, 256>>>((const float4*)Wq, (float2*)wb, nW4);

    qproj_kernel<<<dim3(8, 32), 256>>>();
    attn_kernel<<<dim3(8, 16, 8), 128>>>(M, out);
}

// round 17
// speedup vs baseline: 1.1069x; 1.0098x over previous
#include <cuda_runtime.h>
#include <cuda_bf16.h>
#include <mma.h>
#include <cstdint>

using namespace nvcuda;

#define B_  8
#define S_  512
#define KV_ 2048
#define NH_ 16
#define HD_ 64
#define D_  1024

// bf16 scratch buffers
__device__ __nv_bfloat16 d_kbf[(size_t)B_ * NH_ * KV_ * HD_];     // [bh][kv][d]
__device__ __nv_bfloat16 d_vbf[(size_t)B_ * NH_ * KV_ * HD_];     // [bh][kv][d]
__device__ __nv_bfloat16 d_hbf[(size_t)B_ * S_ * D_];
__device__ __nv_bfloat16 d_wbf[(size_t)D_ * D_];
__device__ __nv_bfloat16 d_qscratch[(size_t)B_ * NH_ * S_ * HD_]; // [bh][s][d]

// ---------------------------------------------------------------------------
// PTX helpers
// ---------------------------------------------------------------------------
__device__ __forceinline__ void ldsm4(uint32_t* r, uint32_t a) {
    asm volatile("ldmatrix.sync.aligned.m8n8.x4.shared.b16 {%0,%1,%2,%3}, [%4];\n"
        : "=r"(r[0]), "=r"(r[1]), "=r"(r[2]), "=r"(r[3]) : "r"(a));
}
__device__ __forceinline__ void ldsm4t(uint32_t* r, uint32_t a) {
    asm volatile("ldmatrix.sync.aligned.m8n8.x4.trans.shared.b16 {%0,%1,%2,%3}, [%4];\n"
        : "=r"(r[0]), "=r"(r[1]), "=r"(r[2]), "=r"(r[3]) : "r"(a));
}
__device__ __forceinline__ void mma16816(float* c, const uint32_t* a, uint32_t b0, uint32_t b1) {
    asm volatile("mma.sync.aligned.m16n8k16.row.col.f32.bf16.bf16.f32 "
        "{%0,%1,%2,%3}, {%4,%5,%6,%7}, {%8,%9}, {%0,%1,%2,%3};\n"
        : "+f"(c[0]), "+f"(c[1]), "+f"(c[2]), "+f"(c[3])
        : "r"(a[0]), "r"(a[1]), "r"(a[2]), "r"(a[3]), "r"(b0), "r"(b1));
}
#define CP16(dst, src) asm volatile("cp.async.cg.shared.global [%0], [%1], 16;\n" :: "r"(dst), "l"(src))
#define CP_COMMIT()    asm volatile("cp.async.commit_group;\n")
#define CP_WAIT0()     asm volatile("cp.async.wait_group 0;\n")

__device__ __forceinline__ uint32_t pack_bf2(float a, float b) {
    __nv_bfloat162 t = __float22bfloat162_rn(make_float2(a, b));
    return *(uint32_t*)&t;
}
#define SWZ128(x) ((x) ^ (((x) >> 3) & 0x70))

// ---------------------------------------------------------------------------
// fp32 -> bf16 conversion, MLP=8: each block converts 2048 float4s, each
// thread issues 8 independent coalesced loads before storing. All array
// sizes here are multiples of 2048 float4s, so no bounds checks.
// ---------------------------------------------------------------------------
__global__ __launch_bounds__(256)
void cvt_kernel(const float4* __restrict__ src, float2* __restrict__ dst, int n4)
{
    const int i0 = blockIdx.x * 2048 + threadIdx.x;
    float4 v[8];
    #pragma unroll
    for (int j = 0; j < 8; j++) v[j] = src[i0 + j * 256];

    #pragma unroll
    for (int j = 0; j < 8; j++) {
        __nv_bfloat162 o[2];
        o[0] = __float22bfloat162_rn(make_float2(v[j].x, v[j].y));
        o[1] = __float22bfloat162_rn(make_float2(v[j].z, v[j].w));
        dst[i0 + j * 256] = *(float2*)o;
    }
}

// ---------------------------------------------------------------------------
// Q projection — byte-identical to R13/R14 (known-good)
// ---------------------------------------------------------------------------
__global__ __launch_bounds__(256)
void qproj_kernel()
{
    __shared__ __align__(16) char smem_raw[2 * 128 * 72 * 2];
    __nv_bfloat16* As = (__nv_bfloat16*)smem_raw;
    __nv_bfloat16* Bs = As + 128 * 72;
    float* Cs = (float*)smem_raw;

    const int n0 = blockIdx.x * 128;
    const int m0 = blockIdx.y * 128;
    const int tid = threadIdx.x;
    const int wid = tid >> 5;
    const int wr = wid & 3;
    const int wc = wid >> 2;

    wmma::fragment<wmma::accumulator, 16, 16, 16, float> acc[2][4];
    #pragma unroll
    for (int i = 0; i < 2; i++)
        #pragma unroll
        for (int j = 0; j < 4; j++) wmma::fill_fragment(acc[i][j], 0.0f);

    for (int kt = 0; kt < 16; kt++) {
        const int k0 = kt * 64;
        for (int i = tid; i < 128 * 8; i += 256) {
            int r = i >> 3, c = (i & 7) * 8;
            *(uint4*)&As[r * 72 + c] = *(const uint4*)(d_hbf + (size_t)(m0 + r) * D_ + k0 + c);
            *(uint4*)&Bs[r * 72 + c] = *(const uint4*)(d_wbf + (size_t)(n0 + r) * D_ + k0 + c);
        }
        __syncthreads();
        #pragma unroll
        for (int ks = 0; ks < 4; ks++) {
            wmma::fragment<wmma::matrix_a, 16, 16, 16, __nv_bfloat16, wmma::row_major> af[2];
            wmma::load_matrix_sync(af[0], &As[(wr * 32 + 0)  * 72 + ks * 16], 72);
            wmma::load_matrix_sync(af[1], &As[(wr * 32 + 16) * 72 + ks * 16], 72);
            #pragma unroll
            for (int j = 0; j < 4; j++) {
                wmma::fragment<wmma::matrix_b, 16, 16, 16, __nv_bfloat16, wmma::col_major> bf;
                wmma::load_matrix_sync(bf, &Bs[(wc * 64 + j * 16) * 72 + ks * 16], 72);
                wmma::mma_sync(acc[0][j], af[0], bf, acc[0][j]);
                wmma::mma_sync(acc[1][j], af[1], bf, acc[1][j]);
            }
        }
        __syncthreads();
    }

    #pragma unroll
    for (int half = 0; half < 2; half++) {
        __syncthreads();
        if ((wr >> 1) == half) {
            const int lr = (wr & 1) * 32;
            #pragma unroll
            for (int i = 0; i < 2; i++)
                #pragma unroll
                for (int j = 0; j < 4; j++)
                    wmma::store_matrix_sync(&Cs[(lr + i * 16) * 132 + wc * 64 + j * 16],
                                            acc[i][j], 132, wmma::mem_row_major);
        }
        __syncthreads();
        for (int i = tid; i < 64 * 16; i += 256) {
            int r = i >> 4, c8 = (i & 15) * 8;
            int gm = m0 + half * 64 + r;
            int gn = n0 + c8;
            int b = gm >> 9, s = gm & 511;
            int h = gn >> 6, d = gn & 63;
            const float* src = &Cs[r * 132 + c8];
            __nv_bfloat162 o[4];
            o[0] = __float22bfloat162_rn(make_float2(src[0], src[1]));
            o[1] = __float22bfloat162_rn(make_float2(src[2], src[3]));
            o[2] = __float22bfloat162_rn(make_float2(src[4], src[5]));
            o[3] = __float22bfloat162_rn(make_float2(src[6], src[7]));
            *(uint4*)(d_qscratch + (((size_t)(b * NH_ + h) * S_ + s) * HD_ + d)) = *(uint4*)o;
        }
    }
}

// ---------------------------------------------------------------------------
// Fused flash attention — byte-identical to R14 passing kernel.
// CTA = 64 queries (4 warps x 16 rows), 128 threads, KV tiles of 64,
// software-pipelined kv-16 chunks (S(c+1) before exp(c)/PV(c)).
// grid (8 s-tiles, 16 heads, 8 batch), 5 CTAs/SM.
// ---------------------------------------------------------------------------
#define NT (KV_ / 64)

__global__ __launch_bounds__(128, 5)
void attn_kernel(const float* __restrict__ Mg_, float* __restrict__ Out)
{
    __shared__ __align__(1024) __nv_bfloat16 sK[2][64 * 64];
    __shared__ __align__(1024) __nv_bfloat16 sV[2][64 * 64];
    __shared__ __align__(16)   float         sM[2][64];

    const int st = blockIdx.x, h = blockIdx.y, b = blockIdx.z;
    const size_t bh = (size_t)b * NH_ + h;
    const __nv_bfloat16* Kh = d_kbf + bh * KV_ * HD_;
    const __nv_bfloat16* Vh = d_vbf + bh * KV_ * HD_;
    const float* Mg = Mg_ + (size_t)b * KV_;

    const int tid = threadIdx.x;
    const int wid = tid >> 5;
    const int lane = tid & 31;

    const uint32_t ks_b = (uint32_t)__cvta_generic_to_shared(sK[0]);
    const uint32_t vs_b = (uint32_t)__cvta_generic_to_shared(sV[0]);
    const uint32_t ms_b = (uint32_t)__cvta_generic_to_shared(sM[0]);

    // one KV tile (K + V + mask) -> swizzled buffer `buf`, one commit group
    auto load_tile = [&](int buf, int kv0) {
        #pragma unroll
        for (int i = 0; i < 4; i++) {
            int idx = tid + i * 128;                 // 512 chunks of 16B
            int r = idx >> 3, c16 = (idx & 7) * 16;
            uint32_t off = (uint32_t)(buf * 8192) + SWZ128((uint32_t)(r * 128 + c16));
            CP16(ks_b + off, Kh + (size_t)(kv0 + r) * HD_ + c16 / 2);
            CP16(vs_b + off, Vh + (size_t)(kv0 + r) * HD_ + c16 / 2);
        }
        if (tid < 16) CP16(ms_b + (uint32_t)(buf * 256 + tid * 16), Mg + kv0 + tid * 4);
    };

    load_tile(0, 0);
    CP_COMMIT();      // group 0

    // Q fragments loaded directly from gmem in the standard mma A-layout
    const int m0 = wid * 16;
    const __nv_bfloat16* Qg = d_qscratch + (bh * S_ + st * 64) * HD_;
    uint32_t qf[4][4];
    {
        const int r0 = m0 + (lane >> 2);
        const int cb = (lane & 3) * 2;
        #pragma unroll
        for (int kb = 0; kb < 4; kb++) {
            qf[kb][0] = *(const uint32_t*)(Qg + (size_t)r0 * HD_ + kb * 16 + cb);
            qf[kb][1] = *(const uint32_t*)(Qg + (size_t)(r0 + 8) * HD_ + kb * 16 + cb);
            qf[kb][2] = *(const uint32_t*)(Qg + (size_t)r0 * HD_ + kb * 16 + cb + 8);
            qf[kb][3] = *(const uint32_t*)(Qg + (size_t)(r0 + 8) * HD_ + kb * 16 + cb + 8);
        }
    }

    float oacc[8][4];
    #pragma unroll
    for (int i = 0; i < 8; i++)
        #pragma unroll
        for (int j = 0; j < 4; j++) oacc[i][j] = 0.0f;
    float rs0 = 0.0f, rs1 = 0.0f;

    // lane-derived ldsm address components
    const int lrow = (lane & 7) + ((lane >> 3) & 1) * 8;   // row within 16-chunk
    const int lcolb = ((lane >> 4) & 1) * 16;              // byte col within 32B

    for (int t = 0; t < NT; t++) {
        const int cur = t & 1;
        const uint32_t kbase = ks_b + (uint32_t)cur * 8192;
        const uint32_t vbase = vs_b + (uint32_t)cur * 8192;
        const float* mrow = sM[cur];

        CP_WAIT0();        // tile t resident
        __syncthreads();   // visible to all warps; WAR fence for buf^1

        if (t + 1 < NT) load_tile(cur ^ 1, (t + 1) * 64);
        CP_COMMIT();

        // S-mma for one kv-16 chunk -> 8 accumulator regs
        auto qk_chunk = [&](int c, float (*sacc)[4]) {
            #pragma unroll
            for (int i = 0; i < 2; i++)
                #pragma unroll
                for (int j = 0; j < 4; j++) sacc[i][j] = 0.0f;
            const int row = c * 16 + lrow;
            #pragma unroll
            for (int kb = 0; kb < 4; kb++) {
                uint32_t kr[4];
                ldsm4(kr, kbase + SWZ128((uint32_t)(row * 128 + kb * 32 + lcolb)));
                mma16816(sacc[0], qf[kb], kr[0], kr[2]);
                mma16816(sacc[1], qf[kb], kr[1], kr[3]);
            }
        };
        // exp + PV for one chunk
        auto exp_pv_chunk = [&](int c, float (*sacc)[4]) {
            uint32_t pf[4];
            #pragma unroll
            for (int ng = 0; ng < 2; ng++) {
                const int c0 = c * 16 + ng * 8 + (lane & 3) * 2;
                float mv0 = mrow[c0], mv1 = mrow[c0 + 1];
                float p0 = __expf(sacc[ng][0] + mv0);
                float p1 = __expf(sacc[ng][1] + mv1);
                float p2 = __expf(sacc[ng][2] + mv0);
                float p3 = __expf(sacc[ng][3] + mv1);
                rs0 += p0 + p1;
                rs1 += p2 + p3;
                pf[ng * 2 + 0] = pack_bf2(p0, p1);
                pf[ng * 2 + 1] = pack_bf2(p2, p3);
            }
            const int vrow = c * 16 + lrow;
            #pragma unroll
            for (int nb2 = 0; nb2 < 4; nb2++) {
                uint32_t vr[4];
                ldsm4t(vr, vbase + SWZ128((uint32_t)(vrow * 128 + nb2 * 32 + lcolb)));
                mma16816(oacc[nb2 * 2 + 0], pf, vr[0], vr[1]);
                mma16816(oacc[nb2 * 2 + 1], pf, vr[2], vr[3]);
            }
        };

        // software pipeline: S(c+1) issued before exp(c)/PV(c)
        float sA[2][4], sB[2][4];
        qk_chunk(0, sA);
        qk_chunk(1, sB);
        exp_pv_chunk(0, sA);
        qk_chunk(2, sA);
        exp_pv_chunk(1, sB);
        qk_chunk(3, sB);
        exp_pv_chunk(2, sA);
        exp_pv_chunk(3, sB);
        // no trailing sync: next iteration's top sync is the WAR fence
    }

    // finalize rowsums across the quad
    rs0 += __shfl_xor_sync(0xffffffffu, rs0, 1);
    rs0 += __shfl_xor_sync(0xffffffffu, rs0, 2);
    rs1 += __shfl_xor_sync(0xffffffffu, rs1, 1);
    rs1 += __shfl_xor_sync(0xffffffffu, rs1, 2);
    const float inv0 = 1.0f / rs0, inv1 = 1.0f / rs1;

    const int row0 = st * 64 + m0 + (lane >> 2);
    const int c0   = (lane & 3) * 2;
    #pragma unroll
    for (int nb = 0; nb < 8; nb++) {
        float2 v0 = make_float2(oacc[nb][0] * inv0, oacc[nb][1] * inv0);
        float2 v1 = make_float2(oacc[nb][2] * inv1, oacc[nb][3] * inv1);
        size_t base0 = ((size_t)(b * S_ + row0) * D_) + h * HD_ + nb * 8 + c0;
        size_t base1 = ((size_t)(b * S_ + row0 + 8) * D_) + h * HD_ + nb * 8 + c0;
        *(float2*)(Out + base0) = v0;
        *(float2*)(Out + base1) = v1;
    }
}

// ---------------------------------------------------------------------------
// Launch — same structure as R13/R14 (4 cvt launches, qproj, attn)
// ---------------------------------------------------------------------------
extern "C" void kernel_launch(void* const* d_in, const int* in_sizes, int n_in,
                              void* d_out, int out_size)
{
    const float* H  = (const float*)d_in[0];  // [8,512,1024]
    const float* Wq = (const float*)d_in[1];  // [1024,1024]
    const float* K  = (const float*)d_in[2];  // [8,16,2048,64]
    const float* V  = (const float*)d_in[3];  // [8,16,2048,64]
    const float* M  = (const float*)d_in[4];  // [8,2048]
    float* out = (float*)d_out;               // [8,512,1024]

    __nv_bfloat16 *kb, *vb, *hb, *wb;
    cudaGetSymbolAddress((void**)&kb, d_kbf);
    cudaGetSymbolAddress((void**)&vb, d_vbf);
    cudaGetSymbolAddress((void**)&hb, d_hbf);
    cudaGetSymbolAddress((void**)&wb, d_wbf);

    const int nKV4 = (B_ * NH_ * KV_ * HD_) / 4;   // 4,194,304
    const int nH4  = (B_ * S_ * D_) / 4;           // 1,048,576
    const int nW4  = (D_ * D_) / 4;                // 262,144

    cvt_kernel<<<nKV4 / 2048, 256>>>((const float4*)K, (float2*)kb, nKV4);
    cvt_kernel<<<nKV4 / 2048, 256>>>((const float4*)V, (float2*)vb, nKV4);
    cvt_kernel<<<nH4 / 2048, 256>>>((const float4*)H, (float2*)hb, nH4);
    cvt_kernel<<<nW4 / 2048, 256>>>((const float4*)Wq, (float2*)wb, nW4);

    qproj_kernel<<<dim3(8, 32), 256>>>();
    attn_kernel<<<dim3(8, 16, 8), 128>>>(M, out);
}